// round 2
// baseline (speedup 1.0000x reference)
#include <cuda_runtime.h>
#include <cstdint>

#define DEVFN __device__ __forceinline__

namespace {
constexpr int Cdim  = 192;
constexpr int NHEAD = 6;
constexpr int HD    = 32;
constexpr int L     = 49;
constexpr int Hdim  = 112;
constexpr int Wdim  = 112;
constexpr int SHIFT = 3;
constexpr int NWIN  = 4096;
constexpr int THREADS = 256;
constexpr int WARPS = 8;

constexpr int SX = 193;                   // odd stride: conflict-free frag loads
constexpr int SP = 57;                    // odd stride for probs / Vt
constexpr int XN_WORDS = L * SX;          // 9457
constexpr int VT_WORDS = NHEAD * HD * SP; // 10944
constexpr int P_WORDS  = NHEAD * L * SP;  // 16758
constexpr int TAILW    = 896;             // covers worst OOB frag read overrun

constexpr int OFF_XN = 0;                 // also reused as attention-out O
constexpr int OFF_Q  = OFF_XN + XN_WORDS;
constexpr int OFF_K  = OFF_Q  + XN_WORDS;
constexpr int OFF_VT = OFF_K  + XN_WORDS;
constexpr int OFF_P  = OFF_VT + VT_WORDS;
constexpr int OFF_TAIL = OFF_P + P_WORDS;
constexpr int SMEM_WORDS = OFF_TAIL + TAILW;
constexpr int SMEM_BYTES = SMEM_WORDS * 4;  // 227,876 B < 232,448 limit
}

// tf32-rounded weight scratch (conversion done once per launch by prep kernel)
__device__ float g_wq[3 * Cdim * Cdim];
__device__ float g_wo[Cdim * Cdim];

DEVFN float tf32r(float x) {
    uint32_t u;
    asm("cvt.rna.tf32.f32 %0, %1;" : "=r"(u) : "f"(x));
    return __uint_as_float(u);
}

DEVFN void mma8(float c[4], uint32_t a0, uint32_t a1, uint32_t a2, uint32_t a3,
                uint32_t b0, uint32_t b1) {
    asm volatile(
        "mma.sync.aligned.m16n8k8.row.col.f32.tf32.tf32.f32 "
        "{%0,%1,%2,%3}, {%4,%5,%6,%7}, {%8,%9}, {%0,%1,%2,%3};"
        : "+f"(c[0]), "+f"(c[1]), "+f"(c[2]), "+f"(c[3])
        : "r"(a0), "r"(a1), "r"(a2), "r"(a3), "r"(b0), "r"(b1));
}

__global__ void prep_weights(const float* __restrict__ wq, const float* __restrict__ wo) {
    int i = blockIdx.x * blockDim.x + threadIdx.x;
    if (i < 3 * Cdim * Cdim) g_wq[i] = tf32r(wq[i]);
    if (i < Cdim * Cdim)     g_wo[i] = tf32r(wo[i]);
}

extern __shared__ float smem_f[];

__global__ void __launch_bounds__(THREADS, 1)
swin_fused(const float* __restrict__ x,
           const float* __restrict__ bqkv,
           const float* __restrict__ bout,
           const float* __restrict__ gamma,
           const float* __restrict__ beta,
           float* __restrict__ out) {
    float* sm = smem_f;
    int* gbase = (int*)(sm + OFF_TAIL);
    const int tid  = threadIdx.x;
    const int lane = tid & 31;
    const int warp = tid >> 5;
    const int g = lane >> 2;   // mma groupID
    const int t = lane & 3;    // mma threadID-in-group

    const int wi = blockIdx.x;
    const int b  = wi >> 8;
    const int wh = (wi >> 4) & 15;
    const int ww = wi & 15;

    // zero Vt (kv pad columns 49..55 must stay 0 for the PV k-padding)
    for (int i = tid; i < VT_WORDS; i += THREADS) sm[OFF_VT + i] = 0.f;

    // ---------------- LayerNorm + shifted-window gather ----------------
    for (int l = warp; l < L; l += WARPS) {
        const int r  = l / 7;
        const int cc = l - r * 7;
        int hh = wh * 7 + r + SHIFT;  if (hh >= Hdim) hh -= Hdim;
        int wp = ww * 7 + cc + SHIFT; if (wp >= Wdim) wp -= Wdim;
        const int base = ((b * Hdim + hh) * Wdim + wp) * Cdim;
        if (lane == 0) gbase[l] = base;
        float v[6];
        float s = 0.f, s2 = 0.f;
#pragma unroll
        for (int i = 0; i < 6; i++) {
            v[i] = x[base + lane + 32 * i];
            s += v[i];
            s2 += v[i] * v[i];
        }
#pragma unroll
        for (int o = 16; o > 0; o >>= 1) {
            s  += __shfl_xor_sync(0xffffffffu, s, o);
            s2 += __shfl_xor_sync(0xffffffffu, s2, o);
        }
        const float mu   = s * (1.f / 192.f);
        const float var  = fmaxf(s2 * (1.f / 192.f) - mu * mu, 0.f);
        const float rstd = rsqrtf(var + 1e-5f);
#pragma unroll
        for (int i = 0; i < 6; i++) {
            const int c = lane + 32 * i;
            sm[OFF_XN + l * SX + c] = tf32r((v[i] - mu) * rstd * gamma[c] + beta[c]);
        }
    }
    __syncthreads();

    // ---------------- QKV projection: Y[49,576] = xn @ Wqkv^T ----------------
    {
        const float rs = 0.17677669529663687f;  // 1/sqrt(hd), folded into q
#pragma unroll 1
        for (int nn = 0; nn < 9; nn++) {
            const int ntile = warp * 9 + nn;           // 72 cols per warp
            const int ncol0 = ntile * 8 + g;
            const float* wptr = g_wq + ncol0 * Cdim + t;
            uint32_t breg[48];                          // full k-strip held in regs
#pragma unroll
            for (int kt = 0; kt < 24; kt++) {
                breg[2 * kt]     = __float_as_uint(wptr[kt * 8]);
                breg[2 * kt + 1] = __float_as_uint(wptr[kt * 8 + 4]);
            }
#pragma unroll
            for (int mt = 0; mt < 4; mt++) {
                float acc[4] = {0.f, 0.f, 0.f, 0.f};
                const float* ap = sm + OFF_XN + (mt * 16 + g) * SX + t;
#pragma unroll
                for (int kt = 0; kt < 24; kt++) {
                    uint32_t a0 = __float_as_uint(ap[kt * 8]);
                    uint32_t a1 = __float_as_uint(ap[8 * SX + kt * 8]);
                    uint32_t a2 = __float_as_uint(ap[kt * 8 + 4]);
                    uint32_t a3 = __float_as_uint(ap[8 * SX + kt * 8 + 4]);
                    mma8(acc, a0, a1, a2, a3, breg[2 * kt], breg[2 * kt + 1]);
                }
#pragma unroll
                for (int i = 0; i < 4; i++) {
                    const int row = mt * 16 + g + ((i >> 1) << 3);
                    const int col = ntile * 8 + 2 * t + (i & 1);
                    if (row < L) {
                        const float val = acc[i] + bqkv[col];
                        if (col < Cdim) {
                            sm[OFF_Q + row * SX + col] = tf32r(val * rs);
                        } else if (col < 2 * Cdim) {
                            sm[OFF_K + row * SX + (col - Cdim)] = tf32r(val);
                        } else {                        // V stored transposed per head
                            const int d = col - 2 * Cdim;
                            sm[OFF_VT + (d >> 5) * (HD * SP) + (d & 31) * SP + row] = tf32r(val);
                        }
                    }
                }
            }
        }
    }
    __syncthreads();

    // ---------------- attention: one warp per head ----------------
    if (warp < NHEAD) {
        const int h = warp;
        float* pp = sm + OFF_P + h * (L * SP);
        const float* qb = sm + OFF_Q + h * HD;
        const float* kb = sm + OFF_K + h * HD;
        // scores S = q @ k^T  (q pre-scaled)
#pragma unroll
        for (int mt = 0; mt < 4; mt++) {
#pragma unroll
            for (int nt = 0; nt < 7; nt++) {
                float acc[4] = {0.f, 0.f, 0.f, 0.f};
#pragma unroll
                for (int kt = 0; kt < 4; kt++) {
                    uint32_t a0 = __float_as_uint(qb[(mt * 16 + g) * SX + kt * 8 + t]);
                    uint32_t a1 = __float_as_uint(qb[(mt * 16 + g + 8) * SX + kt * 8 + t]);
                    uint32_t a2 = __float_as_uint(qb[(mt * 16 + g) * SX + kt * 8 + t + 4]);
                    uint32_t a3 = __float_as_uint(qb[(mt * 16 + g + 8) * SX + kt * 8 + t + 4]);
                    uint32_t b0 = __float_as_uint(kb[(nt * 8 + g) * SX + kt * 8 + t]);
                    uint32_t b1 = __float_as_uint(kb[(nt * 8 + g) * SX + kt * 8 + t + 4]);
                    mma8(acc, a0, a1, a2, a3, b0, b1);
                }
#pragma unroll
                for (int i = 0; i < 4; i++) {
                    const int row = mt * 16 + g + ((i >> 1) << 3);
                    const int col = nt * 8 + 2 * t + (i & 1);
                    if (row < L) pp[row * SP + col] = (col < L) ? acc[i] : 0.f;
                }
            }
        }
        __syncwarp();
        // softmax (fp32), rows distributed across lanes
        for (int r = lane; r < L; r += 32) {
            float* rowp = pp + r * SP;
            float mx = -3.4e38f;
            for (int j = 0; j < L; j++) mx = fmaxf(mx, rowp[j]);
            float ssum = 0.f;
            for (int j = 0; j < L; j++) ssum += __expf(rowp[j] - mx);
            const float inv = 1.f / ssum;
            for (int j = 0; j < L; j++) rowp[j] = tf32r(__expf(rowp[j] - mx) * inv);
        }
        __syncwarp();
        // O_h = P @ V_h   (kv padded to 56, pads are exact zeros)
        const float* vb = sm + OFF_VT + h * (HD * SP);
        float* ob = sm + OFF_XN;  // reuse xn region for attention output
#pragma unroll
        for (int mt = 0; mt < 4; mt++) {
#pragma unroll
            for (int nt = 0; nt < 4; nt++) {
                float acc[4] = {0.f, 0.f, 0.f, 0.f};
#pragma unroll
                for (int kt = 0; kt < 7; kt++) {
                    uint32_t a0 = __float_as_uint(pp[(mt * 16 + g) * SP + kt * 8 + t]);
                    uint32_t a1 = __float_as_uint(pp[(mt * 16 + g + 8) * SP + kt * 8 + t]);
                    uint32_t a2 = __float_as_uint(pp[(mt * 16 + g) * SP + kt * 8 + t + 4]);
                    uint32_t a3 = __float_as_uint(pp[(mt * 16 + g + 8) * SP + kt * 8 + t + 4]);
                    uint32_t b0 = __float_as_uint(vb[(nt * 8 + g) * SP + kt * 8 + t]);
                    uint32_t b1 = __float_as_uint(vb[(nt * 8 + g) * SP + kt * 8 + t + 4]);
                    mma8(acc, a0, a1, a2, a3, b0, b1);
                }
#pragma unroll
                for (int i = 0; i < 4; i++) {
                    const int row = mt * 16 + g + ((i >> 1) << 3);
                    const int col = h * HD + nt * 8 + 2 * t + (i & 1);
                    if (row < L) ob[row * SX + col] = tf32r(acc[i]);
                }
            }
        }
    }
    __syncthreads();

    // ---------------- output projection + bias + residual ----------------
    {
#pragma unroll 1
        for (int nn = 0; nn < 3; nn++) {
            const int ntile = warp * 3 + nn;          // 24 cols per warp
            const int ncol0 = ntile * 8 + g;
            const float* wptr = g_wo + ncol0 * Cdim + t;
            uint32_t breg[48];
#pragma unroll
            for (int kt = 0; kt < 24; kt++) {
                breg[2 * kt]     = __float_as_uint(wptr[kt * 8]);
                breg[2 * kt + 1] = __float_as_uint(wptr[kt * 8 + 4]);
            }
#pragma unroll
            for (int mt = 0; mt < 4; mt++) {
                float acc[4] = {0.f, 0.f, 0.f, 0.f};
                const float* ap = sm + OFF_XN + (mt * 16 + g) * SX + t;
#pragma unroll
                for (int kt = 0; kt < 24; kt++) {
                    uint32_t a0 = __float_as_uint(ap[kt * 8]);
                    uint32_t a1 = __float_as_uint(ap[8 * SX + kt * 8]);
                    uint32_t a2 = __float_as_uint(ap[kt * 8 + 4]);
                    uint32_t a3 = __float_as_uint(ap[8 * SX + kt * 8 + 4]);
                    mma8(acc, a0, a1, a2, a3, breg[2 * kt], breg[2 * kt + 1]);
                }
#pragma unroll
                for (int i = 0; i < 4; i++) {
                    const int row = mt * 16 + g + ((i >> 1) << 3);
                    const int col = ntile * 8 + 2 * t + (i & 1);
                    if (row < L) {
                        const int gb = gbase[row];
                        out[gb + col] = x[gb + col] + acc[i] + bout[col];
                    }
                }
            }
        }
    }
}

extern "C" void kernel_launch(void* const* d_in, const int* in_sizes, int n_in,
                              void* d_out, int out_size) {
    if (n_in < 7) return;  // defensive: metadata contract is 7 tensor inputs
    const float* x     = (const float*)d_in[0];
    const float* w_qkv = (const float*)d_in[1];
    const float* b_qkv = (const float*)d_in[2];
    const float* w_out = (const float*)d_in[3];
    const float* b_out = (const float*)d_in[4];
    const float* gamma = (const float*)d_in[5];
    const float* beta  = (const float*)d_in[6];
    float* out = (float*)d_out;

    cudaFuncSetAttribute(swin_fused, cudaFuncAttributeMaxDynamicSharedMemorySize, SMEM_BYTES);

    prep_weights<<<(3 * Cdim * Cdim + 255) / 256, 256>>>(w_qkv, w_out);
    swin_fused<<<NWIN, THREADS, SMEM_BYTES>>>(x, b_qkv, b_out, gamma, beta, out);
}

// round 3
// speedup vs baseline: 3.2822x; 3.2822x over previous
#include <cuda_runtime.h>
#include <cuda_bf16.h>
#include <cstdint>

#define DEVFN __device__ __forceinline__

namespace {
constexpr int Cdim  = 192;
constexpr int NHEAD = 6;
constexpr int HD    = 32;
constexpr int L     = 49;
constexpr int Hdim  = 112;
constexpr int Wdim  = 112;
constexpr int SHIFT = 3;
constexpr int NWIN  = 4096;
constexpr int THREADS = 512;
constexpr int WARPS = 16;

// bf16-element strides. Byte stride ≡ 16 (mod 128) -> mma operand loads hit
// bank (4g+t): a perfect 32-lane permutation (conflict-free).
constexpr int SXB = 200;   // xn / Q / K / O rows (400 B)
constexpr int SPB = 72;    // P rows and Vt rows (144 B)

constexpr int OFF_XN = 0;                       // 49x200 (also reused as attn-out O)
constexpr int OFF_Q  = OFF_XN + L * SXB;        // 9800
constexpr int OFF_K  = OFF_Q  + L * SXB;        // 19600
constexpr int OFF_VT = OFF_K  + L * SXB;        // 29400 ; 6 heads x [32][72]
constexpr int VT_ELE = NHEAD * HD * SPB;        // 13824
constexpr int OFF_P  = OFF_VT + VT_ELE;         // 43224 ; 6 heads x [49][72]
constexpr int P_HEAD = L * SPB;                 // 3528
constexpr int OFF_TAIL = OFF_P + NHEAD * P_HEAD;// 64392
constexpr int TAIL = 1160;                      // covers last-head OOB frag reads
constexpr int OFF_GB = OFF_TAIL + TAIL;         // 65552 (even -> 4B-aligned bytes)
constexpr int SMEM_BYTES = OFF_GB * 2 + L * 4 + 16;  // ~131.3 KB
}

// weights pre-rounded to bf16 and packed in pairs (one u32 = 2 bf16)
__device__ uint32_t g_wq[3 * Cdim * Cdim / 2];
__device__ uint32_t g_wo[Cdim * Cdim / 2];

DEVFN uint32_t pack_bf2(float lo, float hi) {
    __nv_bfloat162 h = __floats2bfloat162_rn(lo, hi);
    return *reinterpret_cast<uint32_t*>(&h);
}

DEVFN void mma16(float c[4], uint32_t a0, uint32_t a1, uint32_t a2, uint32_t a3,
                 uint32_t b0, uint32_t b1) {
    asm volatile(
        "mma.sync.aligned.m16n8k16.row.col.f32.bf16.bf16.f32 "
        "{%0,%1,%2,%3}, {%4,%5,%6,%7}, {%8,%9}, {%0,%1,%2,%3};"
        : "+f"(c[0]), "+f"(c[1]), "+f"(c[2]), "+f"(c[3])
        : "r"(a0), "r"(a1), "r"(a2), "r"(a3), "r"(b0), "r"(b1));
}

__global__ void prep_weights(const float* __restrict__ wq, const float* __restrict__ wo) {
    int i = blockIdx.x * blockDim.x + threadIdx.x;
    if (i < 3 * Cdim * Cdim / 2) g_wq[i] = pack_bf2(wq[2 * i], wq[2 * i + 1]);
    if (i < Cdim * Cdim / 2)     g_wo[i] = pack_bf2(wo[2 * i], wo[2 * i + 1]);
}

extern __shared__ __nv_bfloat16 smem_h[];

__global__ void __launch_bounds__(THREADS, 1)
swin_fused(const float* __restrict__ x,
           const float* __restrict__ bqkv,
           const float* __restrict__ bout,
           const float* __restrict__ gamma,
           const float* __restrict__ beta,
           float* __restrict__ out) {
    __nv_bfloat16* sm = smem_h;
    int* gbase = (int*)(sm + OFF_GB);
    const int tid  = threadIdx.x;
    const int lane = tid & 31;
    const int warp = tid >> 5;
    const int g = lane >> 2;   // mma groupID (row within fragment)
    const int t = lane & 3;    // mma threadID-in-group

    const int wi = blockIdx.x;
    const int b  = wi >> 8;
    const int wh = (wi >> 4) & 15;
    const int ww = wi & 15;

    // ---- zero Vt + P + tail (pads must be exact zeros; tail must be finite) ----
    {
        uint32_t* z = (uint32_t*)(sm + OFF_VT);
        constexpr int ZW = (VT_ELE + NHEAD * P_HEAD + TAIL) / 2;  // 18076 words
        for (int i = tid; i < ZW; i += THREADS) z[i] = 0u;
    }

    // ---- LayerNorm + shifted-window gather (fp32 math, bf16 packed store) ----
    for (int l = warp; l < L; l += WARPS) {
        const int r  = l / 7;
        const int cc = l - r * 7;
        int hh = wh * 7 + r + SHIFT;  if (hh >= Hdim) hh -= Hdim;
        int wp = ww * 7 + cc + SHIFT; if (wp >= Wdim) wp -= Wdim;
        const int base = ((b * Hdim + hh) * Wdim + wp) * Cdim;
        if (lane == 0) gbase[l] = base;
        const float2* xr = (const float2*)(x + base);
        float2 v[3];
        float s = 0.f, s2 = 0.f;
#pragma unroll
        for (int i = 0; i < 3; i++) {
            v[i] = xr[lane + 32 * i];
            s  += v[i].x + v[i].y;
            s2 += v[i].x * v[i].x + v[i].y * v[i].y;
        }
#pragma unroll
        for (int o = 16; o > 0; o >>= 1) {
            s  += __shfl_xor_sync(0xffffffffu, s, o);
            s2 += __shfl_xor_sync(0xffffffffu, s2, o);
        }
        const float mu   = s * (1.f / 192.f);
        const float var  = fmaxf(s2 * (1.f / 192.f) - mu * mu, 0.f);
        const float rstd = rsqrtf(var + 1e-5f);
        uint32_t* xw = (uint32_t*)(sm + OFF_XN) + l * (SXB / 2);
#pragma unroll
        for (int i = 0; i < 3; i++) {
            const float2 gm = ((const float2*)gamma)[lane + 32 * i];
            const float2 bt = ((const float2*)beta)[lane + 32 * i];
            xw[lane + 32 * i] = pack_bf2((v[i].x - mu) * rstd * gm.x + bt.x,
                                         (v[i].y - mu) * rstd * gm.y + bt.y);
        }
    }
    __syncthreads();

    // ---- QKV projection: [49,192] @ Wqkv^T -> Q,K (row-major) + V (transposed) ----
    {
        const float rs = 0.17677669529663687f;   // 1/sqrt(hd), folded into q
        const uint32_t* aw = (const uint32_t*)(sm + OFF_XN);
        for (int ntile = warp; ntile < 72; ntile += WARPS) {
            const int ncol0 = ntile * 8 + g;
            const uint32_t* wrow = g_wq + ncol0 * (Cdim / 2);
            uint32_t breg[24];
#pragma unroll
            for (int kt = 0; kt < 12; kt++) {
                breg[2 * kt]     = wrow[kt * 8 + t];
                breg[2 * kt + 1] = wrow[kt * 8 + t + 4];
            }
            const float blo = bqkv[ntile * 8 + 2 * t];
            const float bhi = bqkv[ntile * 8 + 2 * t + 1];
            const int seg = ntile / 24;          // 0=Q 1=K 2=V
#pragma unroll 1
            for (int mt = 0; mt < 4; mt++) {
                float acc[4] = {0.f, 0.f, 0.f, 0.f};
                const uint32_t* ap = aw + (mt * 16 + g) * (SXB / 2) + t;
#pragma unroll
                for (int kt = 0; kt < 12; kt++) {
                    mma16(acc, ap[kt * 8], ap[kt * 8 + 8 * (SXB / 2)],
                          ap[kt * 8 + 4], ap[kt * 8 + 4 + 8 * (SXB / 2)],
                          breg[2 * kt], breg[2 * kt + 1]);
                }
                const int row0 = mt * 16 + g;
                float v0 = acc[0] + blo, v1 = acc[1] + bhi;
                float v2 = acc[2] + blo, v3 = acc[3] + bhi;
                if (seg == 0) {
                    v0 *= rs; v1 *= rs; v2 *= rs; v3 *= rs;
                    uint32_t* qw = (uint32_t*)(sm + OFF_Q);
                    const int cw = ntile * 4 + t;
                    if (row0 < L)     qw[row0 * (SXB / 2) + cw]       = pack_bf2(v0, v1);
                    if (row0 + 8 < L) qw[(row0 + 8) * (SXB / 2) + cw] = pack_bf2(v2, v3);
                } else if (seg == 1) {
                    uint32_t* kw = (uint32_t*)(sm + OFF_K);
                    const int cw = (ntile - 24) * 4 + t;
                    if (row0 < L)     kw[row0 * (SXB / 2) + cw]       = pack_bf2(v0, v1);
                    if (row0 + 8 < L) kw[(row0 + 8) * (SXB / 2) + cw] = pack_bf2(v2, v3);
                } else {
                    // V transposed per head: Vt[head][d][token]
                    const int d0 = (ntile - 48) * 8 + 2 * t;
                    __nv_bfloat16* vt0 = sm + OFF_VT + (d0 >> 5) * (HD * SPB) + (d0 & 31) * SPB;
                    __nv_bfloat16* vt1 = vt0 + SPB;   // d0+1 stays in same head (d0 even)
                    if (row0 < L)     { vt0[row0] = __float2bfloat16(v0);
                                        vt1[row0] = __float2bfloat16(v1); }
                    if (row0 + 8 < L) { vt0[row0 + 8] = __float2bfloat16(v2);
                                        vt1[row0 + 8] = __float2bfloat16(v3); }
                }
            }
        }
    }
    __syncthreads();

    // ---- scores: S = q @ k^T  (12 warps: 2 per head, 2 m-tiles each) ----
    if (warp < 12) {
        const int h = warp >> 1;
        const int mtb = (warp & 1) * 2;
        const uint32_t* qb = (const uint32_t*)(sm + OFF_Q) + h * (HD / 2);
        const uint32_t* kb = (const uint32_t*)(sm + OFF_K) + h * (HD / 2);
        uint32_t* pw = (uint32_t*)(sm + OFF_P) + h * (P_HEAD / 2);
#pragma unroll
        for (int mi = 0; mi < 2; mi++) {
            const int mt = mtb + mi;
#pragma unroll
            for (int nt = 0; nt < 7; nt++) {
                float acc[4] = {0.f, 0.f, 0.f, 0.f};
#pragma unroll
                for (int kt = 0; kt < 2; kt++) {
                    uint32_t a0 = qb[(mt * 16 + g) * (SXB / 2) + kt * 8 + t];
                    uint32_t a1 = qb[(mt * 16 + g + 8) * (SXB / 2) + kt * 8 + t];
                    uint32_t a2 = qb[(mt * 16 + g) * (SXB / 2) + kt * 8 + t + 4];
                    uint32_t a3 = qb[(mt * 16 + g + 8) * (SXB / 2) + kt * 8 + t + 4];
                    uint32_t b0 = kb[(nt * 8 + g) * (SXB / 2) + kt * 8 + t];
                    uint32_t b1 = kb[(nt * 8 + g) * (SXB / 2) + kt * 8 + t + 4];
                    mma16(acc, a0, a1, a2, a3, b0, b1);
                }
                const int row0 = mt * 16 + g;
                const int c0 = nt * 8 + 2 * t;
                const float s0 = (c0 < L) ? acc[0] : 0.f;
                const float s1 = (c0 + 1 < L) ? acc[1] : 0.f;
                const float s2 = (c0 < L) ? acc[2] : 0.f;
                const float s3 = (c0 + 1 < L) ? acc[3] : 0.f;
                const int cw = nt * 4 + t;
                if (row0 < L)     pw[row0 * (SPB / 2) + cw]       = pack_bf2(s0, s1);
                if (row0 + 8 < L) pw[(row0 + 8) * (SPB / 2) + cw] = pack_bf2(s2, s3);
            }
        }
    }
    __syncthreads();

    // ---- softmax (fp32): warp per (head, row-half), conflict-free loads ----
    if (warp < 12) {
        const int h = warp >> 1;
        const int r0 = (warp & 1) ? 25 : 0;
        const int r1 = (warp & 1) ? 48 : 24;
        __nv_bfloat16* ph = sm + OFF_P + h * P_HEAD;
        for (int r = r0; r <= r1; r++) {
            __nv_bfloat16* rp = ph + r * SPB;
            const float v0 = __bfloat162float(rp[lane]);
            const float v1 = (lane < 17) ? __bfloat162float(rp[lane + 32]) : -1e30f;
            float m = fmaxf(v0, v1);
#pragma unroll
            for (int o = 16; o > 0; o >>= 1) m = fmaxf(m, __shfl_xor_sync(0xffffffffu, m, o));
            const float e0 = __expf(v0 - m);
            const float e1 = (lane < 17) ? __expf(v1 - m) : 0.f;
            float s = e0 + e1;
#pragma unroll
            for (int o = 16; o > 0; o >>= 1) s += __shfl_xor_sync(0xffffffffu, s, o);
            const float inv = 1.f / s;
            rp[lane] = __float2bfloat16(e0 * inv);
            if (lane < 17) rp[lane + 32] = __float2bfloat16(e1 * inv);
        }
    }
    __syncthreads();

    // ---- O = P @ V  (keys padded to 64; P pad cols are exact zeros) ----
    if (warp < 12) {
        const int h = warp >> 1;
        const int mtb = (warp & 1) * 2;
        const uint32_t* pr = (const uint32_t*)(sm + OFF_P) + h * (P_HEAD / 2);
        const uint32_t* vb = (const uint32_t*)(sm + OFF_VT) + h * (HD * SPB / 2);
        uint32_t* ow = (uint32_t*)(sm + OFF_XN);
#pragma unroll
        for (int mi = 0; mi < 2; mi++) {
            const int mt = mtb + mi;
#pragma unroll
            for (int nt = 0; nt < 4; nt++) {
                float acc[4] = {0.f, 0.f, 0.f, 0.f};
#pragma unroll
                for (int kt = 0; kt < 4; kt++) {
                    uint32_t a0 = pr[(mt * 16 + g) * (SPB / 2) + kt * 8 + t];
                    uint32_t a1 = pr[(mt * 16 + g + 8) * (SPB / 2) + kt * 8 + t];
                    uint32_t a2 = pr[(mt * 16 + g) * (SPB / 2) + kt * 8 + t + 4];
                    uint32_t a3 = pr[(mt * 16 + g + 8) * (SPB / 2) + kt * 8 + t + 4];
                    uint32_t b0 = vb[(nt * 8 + g) * (SPB / 2) + kt * 8 + t];
                    uint32_t b1 = vb[(nt * 8 + g) * (SPB / 2) + kt * 8 + t + 4];
                    mma16(acc, a0, a1, a2, a3, b0, b1);
                }
                const int row0 = mt * 16 + g;
                const int cw = h * (HD / 2) + nt * 4 + t;
                if (row0 < L)     ow[row0 * (SXB / 2) + cw]       = pack_bf2(acc[0], acc[1]);
                if (row0 + 8 < L) ow[(row0 + 8) * (SXB / 2) + cw] = pack_bf2(acc[2], acc[3]);
            }
        }
    }
    __syncthreads();

    // ---- output projection + bias + residual (fp32 epilogue, float2 I/O) ----
    {
        const uint32_t* aw = (const uint32_t*)(sm + OFF_XN);
        for (int ntile = warp; ntile < 24; ntile += WARPS) {
            const int ncol0 = ntile * 8 + g;
            const uint32_t* wrow = g_wo + ncol0 * (Cdim / 2);
            uint32_t breg[24];
#pragma unroll
            for (int kt = 0; kt < 12; kt++) {
                breg[2 * kt]     = wrow[kt * 8 + t];
                breg[2 * kt + 1] = wrow[kt * 8 + t + 4];
            }
            const float blo = bout[ntile * 8 + 2 * t];
            const float bhi = bout[ntile * 8 + 2 * t + 1];
#pragma unroll 1
            for (int mt = 0; mt < 4; mt++) {
                float acc[4] = {0.f, 0.f, 0.f, 0.f};
                const uint32_t* ap = aw + (mt * 16 + g) * (SXB / 2) + t;
#pragma unroll
                for (int kt = 0; kt < 12; kt++) {
                    mma16(acc, ap[kt * 8], ap[kt * 8 + 8 * (SXB / 2)],
                          ap[kt * 8 + 4], ap[kt * 8 + 4 + 8 * (SXB / 2)],
                          breg[2 * kt], breg[2 * kt + 1]);
                }
                const int row0 = mt * 16 + g;
                const int c0 = ntile * 8 + 2 * t;
                if (row0 < L) {
                    const int gb = gbase[row0];
                    const float2 res = *(const float2*)(x + gb + c0);
                    float2 o2 = make_float2(res.x + acc[0] + blo, res.y + acc[1] + bhi);
                    *(float2*)(out + gb + c0) = o2;
                }
                if (row0 + 8 < L) {
                    const int gb = gbase[row0 + 8];
                    const float2 res = *(const float2*)(x + gb + c0);
                    float2 o2 = make_float2(res.x + acc[2] + blo, res.y + acc[3] + bhi);
                    *(float2*)(out + gb + c0) = o2;
                }
            }
        }
    }
}

extern "C" void kernel_launch(void* const* d_in, const int* in_sizes, int n_in,
                              void* d_out, int out_size) {
    if (n_in < 7) return;
    const float* x     = (const float*)d_in[0];
    const float* w_qkv = (const float*)d_in[1];
    const float* b_qkv = (const float*)d_in[2];
    const float* w_out = (const float*)d_in[3];
    const float* b_out = (const float*)d_in[4];
    const float* gamma = (const float*)d_in[5];
    const float* beta  = (const float*)d_in[6];
    float* out = (float*)d_out;

    cudaFuncSetAttribute(swin_fused, cudaFuncAttributeMaxDynamicSharedMemorySize, SMEM_BYTES);

    prep_weights<<<(3 * Cdim * Cdim / 2 + 255) / 256, 256>>>(w_qkv, w_out);
    swin_fused<<<NWIN, THREADS, SMEM_BYTES>>>(x, b_qkv, b_out, gamma, beta, out);
}